// round 8
// baseline (speedup 1.0000x reference)
#include <cuda_runtime.h>
#include <cuda_fp16.h>
#include <cstdint>

#define N_NODES 8192
#define D_FEAT  128
#define C_CLS   10
#define T_TRAIN 1024
#define ND (N_NODES * D_FEAT)

#define INV_SCALE (1.0f / 4096.0f)

// ---------------- scratch (device globals; no allocation allowed) ----------------
__device__ __align__(128) float  g_S[N_NODES * 256];     // [s_r|s_i] node-major [8192,256]
__device__ __align__(128) __half g_STh[256 * N_NODES];   // S^T fp16 [256,8192] K-major (GEMM B)
__device__ __align__(128) float  g_P[4 * N_NODES * 256]; // K-split partial sums (4 splits)
__device__ __align__(128) float  g_Msg[N_NODES * 256];   // combined msg [8192,256]
__device__ __align__(128) float  g_in[2 * N_NODES];      // in_r, in_i
__device__ __align__(128) float  g_pn[N_NODES * C_CLS];  // pseudo_norm
__device__ __align__(128) float  g_Wbig[256 * 256];      // [[Wr,-Wi],[Wi,Wr]] K-major

// ---------------- helpers ----------------
__device__ __forceinline__ void cp16(uint32_t smem, const void* g) {
    asm volatile("cp.async.cg.shared.global [%0], [%1], 16;\n" :: "r"(smem), "l"(g));
}
// exact x4096 via exponent add (adj >= 0; 0 -> tiny -> rounds to +0 in f16)
__device__ __forceinline__ uint32_t packh2_scaled(float x, float y) {
    float xs = __uint_as_float(__float_as_uint(x) + 0x06000000u);
    float ys = __uint_as_float(__float_as_uint(y) + 0x06000000u);
    __half2 h = __floats2half2_rn(xs, ys);
    return *reinterpret_cast<uint32_t*>(&h);
}

// ---------------- K0: build combined MLP weight ----------------
__global__ void k_build_wbig(const float* __restrict__ Wr, const float* __restrict__ Wi) {
    int idx = blockIdx.x * 256 + threadIdx.x;
    int d = idx >> 8, e = idx & 255;
    float v;
    if (d < 128) v = (e < 128) ? Wr[d * 128 + e] : -Wi[d * 128 + (e - 128)];
    else {
        int dd = d - 128;
        v = (e < 128) ? Wi[dd * 128 + e] : Wr[dd * 128 + (e - 128)];
    }
    g_Wbig[idx] = v;
}

// ---------------- K1: per-node prep ----------------
__global__ __launch_bounds__(256) void k_node_prep(
    const float* __restrict__ xr_g, const float* __restrict__ xi_g,
    const float* __restrict__ Wcr, const float* __restrict__ Wci,
    const float* __restrict__ bcr, const float* __restrict__ bci,
    const float* __restrict__ thr, const float* __restrict__ thi)
{
    __shared__ float sWr[C_CLS * 128], sWi[C_CLS * 128];
    __shared__ float sb[4 * C_CLS];
    int tid = threadIdx.x;
    for (int i = tid; i < C_CLS * 128; i += 256) { sWr[i] = Wcr[i]; sWi[i] = Wci[i]; }
    if (tid < C_CLS) {
        sb[tid] = bcr[tid]; sb[C_CLS + tid] = bci[tid];
        sb[2 * C_CLS + tid] = thr[tid]; sb[3 * C_CLS + tid] = thi[tid];
    }
    __syncthreads();

    int wid = tid >> 5, lane = tid & 31;
    int j = blockIdx.x * 8 + wid;

    float xr[4], xi[4];
#pragma unroll
    for (int k = 0; k < 4; k++) {
        xr[k] = xr_g[j * 128 + lane + 32 * k];
        xi[k] = xi_g[j * 128 + lane + 32 * k];
    }

    float pn[C_CLS];
#pragma unroll
    for (int c = 0; c < C_CLS; c++) {
        float p1 = 0.f, p2 = 0.f, p3 = 0.f, p4 = 0.f;
#pragma unroll
        for (int k = 0; k < 4; k++) {
            float wr = sWr[c * 128 + lane + 32 * k];
            float wi = sWi[c * 128 + lane + 32 * k];
            p1 += xr[k] * wr; p2 += xi[k] * wr;
            p3 += xi[k] * wi; p4 += xr[k] * wi;
        }
#pragma unroll
        for (int off = 16; off; off >>= 1) {
            p1 += __shfl_xor_sync(0xffffffffu, p1, off);
            p2 += __shfl_xor_sync(0xffffffffu, p2, off);
            p3 += __shfl_xor_sync(0xffffffffu, p3, off);
            p4 += __shfl_xor_sync(0xffffffffu, p4, off);
        }
        float cr = p1 + sb[c] - p3 - sb[C_CLS + c];
        float ci = p2 + sb[c] + p4 + sb[C_CLS + c];
        pn[c] = sqrtf(cr * cr + ci * ci);
    }

    float m = pn[0];
#pragma unroll
    for (int c = 1; c < C_CLS; c++) m = fmaxf(m, pn[c]);
    float s = 0.f, e[C_CLS];
#pragma unroll
    for (int c = 0; c < C_CLS; c++) { e[c] = expf(pn[c] - m); s += e[c]; }
    float inv = 1.0f / s, inr = 0.f, ini = 0.f;
#pragma unroll
    for (int c = 0; c < C_CLS; c++) {
        float sc = e[c] * inv;
        inr += sc * sb[2 * C_CLS + c];
        ini += sc * sb[3 * C_CLS + c];
    }

    if (lane == 0) {
#pragma unroll
        for (int c = 0; c < C_CLS; c++) g_pn[j * C_CLS + c] = pn[c];
        g_in[j] = inr; g_in[N_NODES + j] = ini;
    }

#pragma unroll
    for (int k = 0; k < 4; k++) {
        int d = lane + 32 * k;
        g_S[j * 256 + d]       = inr * xr[k] + ini * xi[k];
        g_S[j * 256 + 128 + d] = inr * xi[k] - ini * xr[k];
    }
}

// ---------------- K1b: transpose g_S [8192,256] f32 -> g_STh [256,8192] f16 ----------------
__global__ void k_transp() {
    __shared__ float t[32][33];
    int bx = blockIdx.x;
    int by = blockIdx.y;
    int lx = threadIdx.x, ly = threadIdx.y;
#pragma unroll
    for (int i = 0; i < 32; i += 8)
        t[ly + i][lx] = g_S[(size_t)(bx * 32 + ly + i) * 256 + by * 32 + lx];
    __syncthreads();
#pragma unroll
    for (int i = 0; i < 32; i += 8)
        g_STh[(size_t)(by * 32 + ly + i) * N_NODES + bx * 32 + lx] = __float2half(t[lx][ly + i]);
}

// ================= GEMM1: fp16 mma.sync, 128x128 tiles, 2 CTAs/SM, Ksplit=4 =================
#define BM 128
#define BN 128
#define BK 32
#define NSPLIT 4
#define KSPLIT (N_NODES / NSPLIT)    // 2048
#define NKT (KSPLIT / BK)            // 64
#define NSTG 3
#define ASTR 40                      // floats per A smem row (160B)
#define BSTR 40                      // halfs per B smem row (80B)
#define ASTAGE (BM * ASTR)           // floats/stage
#define BSTAGE (BN * BSTR)           // halfs/stage
#define SMEM_G1 (NSTG * (ASTAGE * 4 + BSTAGE * 2))   // 92160 B -> 2 CTAs/SM

__global__ __launch_bounds__(256, 2) void k_gemm1(const float* __restrict__ adj) {
    extern __shared__ __align__(16) char smraw[];
    float*  As = reinterpret_cast<float*>(smraw);
    __half* Bs = reinterpret_cast<__half*>(smraw + NSTG * ASTAGE * 4);

    int tid = threadIdx.x;
    int m0 = blockIdx.x * BM;
    int n0 = blockIdx.y * BN;
    int kb = blockIdx.z * KSPLIT;
    const float*  Ag = adj + (size_t)m0 * N_NODES + kb;
    const __half* Bg = g_STh + (size_t)n0 * N_NODES + kb;

    uint32_t sA = (uint32_t)__cvta_generic_to_shared(As);
    uint32_t sB = (uint32_t)__cvta_generic_to_shared(Bs);

    auto loadst = [&](int kt) {
        int st = kt % NSTG;
        int k0 = kt * BK;
#pragma unroll
        for (int i = 0; i < 4; i++) {               // A: 128 rows x 8 vec16 = 1024
            int v = tid + i * 256;
            int r = v >> 3, c = v & 7;
            cp16(sA + (uint32_t)(st * ASTAGE + r * ASTR + c * 4) * 4,
                 Ag + (size_t)r * N_NODES + k0 + c * 4);
        }
#pragma unroll
        for (int i = 0; i < 2; i++) {               // B: 128 rows x 4 vec16 = 512
            int v = tid + i * 256;
            int r = v >> 2, c = v & 3;
            cp16(sB + (uint32_t)(st * BSTAGE + r * BSTR + c * 8) * 2,
                 Bg + (size_t)r * N_NODES + k0 + c * 8);
        }
        asm volatile("cp.async.commit_group;\n");
    };

    float acc[2][8][4];
#pragma unroll
    for (int a = 0; a < 2; a++)
#pragma unroll
        for (int b = 0; b < 8; b++)
#pragma unroll
            for (int c = 0; c < 4; c++) acc[a][b][c] = 0.f;

    int wid = tid >> 5, lane = tid & 31;
    int wm = (wid & 3) * 32;        // warp grid 4(m) x 2(n), warp tile 32x64
    int wn = (wid >> 2) * 64;
    int g = lane >> 2, tg = lane & 3;

    loadst(0); loadst(1);
    for (int kt = 0; kt < NKT; kt++) {
        asm volatile("cp.async.wait_group 1;\n");
        __syncthreads();
        if (kt + 2 < NKT) loadst(kt + 2);

        const float*  as = As + (kt % NSTG) * ASTAGE;
        const __half* bs = Bs + (kt % NSTG) * BSTAGE;
#pragma unroll
        for (int kk = 0; kk < 2; kk++) {
            int k0 = kk * 16;
            uint32_t a[2][4], b[8][2];
#pragma unroll
            for (int mf = 0; mf < 2; mf++) {
                int rb = wm + mf * 16;
                const float* p0 = as + (rb + g) * ASTR + k0 + 2 * tg;
                const float* p1 = p0 + 8 * ASTR;
                float2 f0 = *reinterpret_cast<const float2*>(p0);
                float2 f1 = *reinterpret_cast<const float2*>(p1);
                float2 f2 = *reinterpret_cast<const float2*>(p0 + 8);
                float2 f3 = *reinterpret_cast<const float2*>(p1 + 8);
                a[mf][0] = packh2_scaled(f0.x, f0.y);
                a[mf][1] = packh2_scaled(f1.x, f1.y);
                a[mf][2] = packh2_scaled(f2.x, f2.y);
                a[mf][3] = packh2_scaled(f3.x, f3.y);
            }
#pragma unroll
            for (int nf = 0; nf < 8; nf++) {
                int nr = wn + nf * 8 + g;
                b[nf][0] = *reinterpret_cast<const uint32_t*>(bs + nr * BSTR + k0 + 2 * tg);
                b[nf][1] = *reinterpret_cast<const uint32_t*>(bs + nr * BSTR + k0 + 2 * tg + 8);
            }
#pragma unroll
            for (int nf = 0; nf < 8; nf++)
#pragma unroll
                for (int mf = 0; mf < 2; mf++) {
                    asm volatile(
                        "mma.sync.aligned.m16n8k16.row.col.f32.f16.f16.f32 "
                        "{%0,%1,%2,%3}, {%4,%5,%6,%7}, {%8,%9}, {%0,%1,%2,%3};\n"
                        : "+f"(acc[mf][nf][0]), "+f"(acc[mf][nf][1]),
                          "+f"(acc[mf][nf][2]), "+f"(acc[mf][nf][3])
                        : "r"(a[mf][0]), "r"(a[mf][1]), "r"(a[mf][2]), "r"(a[mf][3]),
                          "r"(b[nf][0]), "r"(b[nf][1]));
                }
        }
    }

    // epilogue: raw partial store
    float* P = g_P + (size_t)blockIdx.z * (N_NODES * 256);
#pragma unroll
    for (int mf = 0; mf < 2; mf++)
#pragma unroll
        for (int nf = 0; nf < 8; nf++) {
            int row = m0 + wm + mf * 16 + g;
            int col = n0 + wn + nf * 8 + 2 * tg;
            P[(size_t)row * 256 + col]           = acc[mf][nf][0];
            P[(size_t)row * 256 + col + 1]       = acc[mf][nf][1];
            P[(size_t)(row + 8) * 256 + col]     = acc[mf][nf][2];
            P[(size_t)(row + 8) * 256 + col + 1] = acc[mf][nf][3];
        }
}

// ---------------- K2b: msg = diag(in) * (P0+P1+P2+P3) / SCALE ----------------
__global__ void k_combine2() {
    int t = blockIdx.x * 256 + threadIdx.x;
    int n = t >> 7, d = t & 127;
    size_t b = (size_t)n * 256;
    const size_t PS = (size_t)N_NODES * 256;
    float mr = (g_P[b + d] + g_P[PS + b + d] + g_P[2 * PS + b + d] + g_P[3 * PS + b + d]) * INV_SCALE;
    float mi = (g_P[b + 128 + d] + g_P[PS + b + 128 + d] + g_P[2 * PS + b + 128 + d] + g_P[3 * PS + b + 128 + d]) * INV_SCALE;
    float inr = g_in[n], ini = g_in[N_NODES + n];
    g_Msg[b + d]       = inr * mr - ini * mi;
    g_Msg[b + 128 + d] = inr * mi + ini * mr;
}

// ---------------- K3: MLP GEMM (tf32, fused bias+residual+split) ----------------
#define KT   16
#define SROW 20

__global__ __launch_bounds__(256) void k_gemm_mlp(
    const float* __restrict__ br, const float* __restrict__ bi,
    const float* __restrict__ xr, const float* __restrict__ xi,
    float* __restrict__ out)
{
    __shared__ __align__(16) float As2[2][128 * SROW];
    __shared__ __align__(16) float Bs2[2][128 * SROW];

    const float* A = g_Msg; const float* B = g_Wbig;
    const int lda = 256, ldb = 256, nk = 256 / KT;

    int tid = threadIdx.x;
    int m0 = blockIdx.x * 128;
    int n0 = blockIdx.y * 128;
    const float* Ag = A + (size_t)m0 * lda;
    const float* Bg = B + (size_t)n0 * ldb;

    uint32_t sA = (uint32_t)__cvta_generic_to_shared(&As2[0][0]);
    uint32_t sB = (uint32_t)__cvta_generic_to_shared(&Bs2[0][0]);

    auto load_stage = [&](int buf, int kt) {
        int k0 = kt * KT;
#pragma unroll
        for (int i = 0; i < 2; i++) {
            int v = tid + i * 256;
            int r = v >> 2, c4 = v & 3;
            cp16(sA + (uint32_t)(buf * 128 * SROW + r * SROW + c4 * 4) * 4,
                 Ag + (size_t)r * lda + k0 + c4 * 4);
            cp16(sB + (uint32_t)(buf * 128 * SROW + r * SROW + c4 * 4) * 4,
                 Bg + (size_t)r * ldb + k0 + c4 * 4);
        }
        asm volatile("cp.async.commit_group;\n");
    };

    float acc[2][8][4];
#pragma unroll
    for (int a = 0; a < 2; a++)
#pragma unroll
        for (int b = 0; b < 8; b++)
#pragma unroll
            for (int c = 0; c < 4; c++) acc[a][b][c] = 0.f;

    int wid = tid >> 5, lane = tid & 31;
    int wm = (wid & 3) * 32;
    int wn = (wid >> 2) * 64;
    int g = lane >> 2, tg = lane & 3;

    load_stage(0, 0);
    for (int kt = 0; kt < nk; kt++) {
        if (kt + 1 < nk) {
            load_stage((kt + 1) & 1, kt + 1);
            asm volatile("cp.async.wait_group 1;\n");
        } else {
            asm volatile("cp.async.wait_group 0;\n");
        }
        __syncthreads();
        const float* as = &As2[kt & 1][0];
        const float* bs = &Bs2[kt & 1][0];
#pragma unroll
        for (int k8 = 0; k8 < 2; k8++) {
            uint32_t a[2][4], b[8][2];
#pragma unroll
            for (int mf = 0; mf < 2; mf++) {
                int rb = wm + mf * 16;
                a[mf][0] = __float_as_uint(as[(rb + g)     * SROW + k8 * 8 + tg]);
                a[mf][1] = __float_as_uint(as[(rb + g + 8) * SROW + k8 * 8 + tg]);
                a[mf][2] = __float_as_uint(as[(rb + g)     * SROW + k8 * 8 + tg + 4]);
                a[mf][3] = __float_as_uint(as[(rb + g + 8) * SROW + k8 * 8 + tg + 4]);
            }
#pragma unroll
            for (int nf = 0; nf < 8; nf++) {
                int cb = wn + nf * 8;
                b[nf][0] = __float_as_uint(bs[(cb + g) * SROW + k8 * 8 + tg]);
                b[nf][1] = __float_as_uint(bs[(cb + g) * SROW + k8 * 8 + tg + 4]);
            }
#pragma unroll
            for (int mf = 0; mf < 2; mf++)
#pragma unroll
                for (int nf = 0; nf < 8; nf++) {
                    asm volatile(
                        "mma.sync.aligned.m16n8k8.row.col.f32.tf32.tf32.f32 "
                        "{%0,%1,%2,%3}, {%4,%5,%6,%7}, {%8,%9}, {%0,%1,%2,%3};\n"
                        : "+f"(acc[mf][nf][0]), "+f"(acc[mf][nf][1]),
                          "+f"(acc[mf][nf][2]), "+f"(acc[mf][nf][3])
                        : "r"(a[mf][0]), "r"(a[mf][1]), "r"(a[mf][2]), "r"(a[mf][3]),
                          "r"(b[nf][0]), "r"(b[nf][1]));
                }
        }
        __syncthreads();
    }

#pragma unroll
    for (int mf = 0; mf < 2; mf++)
#pragma unroll
        for (int nf = 0; nf < 8; nf++) {
            int row = m0 + wm + mf * 16 + g;
            int col = n0 + wn + nf * 8 + 2 * tg;
#pragma unroll
            for (int q = 0; q < 4; q++) {
                int r = row + (q >> 1) * 8;
                int c = col + (q & 1);
                float v = acc[mf][nf][q];
                if (c < 128) {
                    out[(size_t)r * 128 + c] =
                        v + br[c] - bi[c] + xr[(size_t)r * 128 + c];
                } else {
                    int cc = c - 128;
                    out[(size_t)ND + (size_t)r * 128 + cc] =
                        v + br[cc] + bi[cc] + xi[(size_t)r * 128 + cc];
                }
            }
        }
}

// ---------------- K4: losses ----------------
__global__ void k_losses(const float* __restrict__ thi,
                         const int* __restrict__ labels,
                         const int* __restrict__ tidx,
                         float* __restrict__ out)
{
    __shared__ float red[256];
    int tid = threadIdx.x;

    if (tid == 0) {
        float st[C_CLS];
        for (int c = 0; c < C_CLS; c++) st[c] = thi[c];
        for (int i = 1; i < C_CLS; i++) {
            float key = st[i]; int k = i - 1;
            while (k >= 0 && st[k] > key) { st[k + 1] = st[k]; k--; }
            st[k + 1] = key;
        }
        float sum = 0.f, mx = 0.f;
        for (int c = 0; c < C_CLS - 1; c++) {
            float d = fabsf(st[c + 1] - st[c]);
            sum += d; if (d > mx) mx = d;
        }
        float difference = sum / (mx + 1e-6f);
        out[(size_t)2 * ND] = 0.1f / (1e-6f + difference);
    }

    float accn = 0.f;
    for (int t = tid; t < T_TRAIN; t += 256) {
        int row = tidx[t];
        int lab = labels[row];
        float l[C_CLS]; float m = -1e30f;
#pragma unroll
        for (int c = 0; c < C_CLS; c++) { l[c] = g_pn[row * C_CLS + c]; m = fmaxf(m, l[c]); }
        float s = 0.f;
#pragma unroll
        for (int c = 0; c < C_CLS; c++) s += expf(l[c] - m);
        float lse = m + logf(s);
        float lp = 0.f;
#pragma unroll
        for (int c = 0; c < C_CLS; c++) if (c == lab) lp = l[c] - lse;
        accn += -lp;
    }
    red[tid] = accn;
    __syncthreads();
    for (int off = 128; off; off >>= 1) {
        if (tid < off) red[tid] += red[tid + off];
        __syncthreads();
    }
    if (tid == 0) out[(size_t)2 * ND + 1] = red[0] / (float)T_TRAIN * 0.1f;
}

// ---------------- launch ----------------
extern "C" void kernel_launch(void* const* d_in, const int* in_sizes, int n_in,
                              void* d_out, int out_size)
{
    const float* x_real     = (const float*)d_in[0];
    const float* x_imag     = (const float*)d_in[1];
    const float* adj        = (const float*)d_in[2];
    const float* theta_real = (const float*)d_in[3];
    const float* theta_imag = (const float*)d_in[4];
    const float* W_r        = (const float*)d_in[5];
    const float* b_r        = (const float*)d_in[6];
    const float* W_i        = (const float*)d_in[7];
    const float* b_i        = (const float*)d_in[8];
    const float* Wc_r       = (const float*)d_in[9];
    const float* bc_r       = (const float*)d_in[10];
    const float* Wc_i       = (const float*)d_in[11];
    const float* bc_i       = (const float*)d_in[12];
    const int*   labels     = (const int*)d_in[13];
    const int*   train_idx  = (const int*)d_in[14];
    float* out = (float*)d_out;

    cudaFuncSetAttribute(k_gemm1, cudaFuncAttributeMaxDynamicSharedMemorySize, SMEM_G1);

    k_build_wbig<<<256, 256>>>(W_r, W_i);
    k_node_prep<<<1024, 256>>>(x_real, x_imag, Wc_r, Wc_i, bc_r, bc_i,
                               theta_real, theta_imag);
    k_transp<<<dim3(256, 8), dim3(32, 8)>>>();
    k_gemm1<<<dim3(64, 2, 4), 256, SMEM_G1>>>(adj);
    k_combine2<<<4096, 256>>>();
    k_gemm_mlp<<<dim3(64, 2), 256>>>(b_r, b_i, x_real, x_imag, out);
    k_losses<<<1, 256>>>(theta_imag, labels, train_idx, out);
}

// round 9
// speedup vs baseline: 1.0225x; 1.0225x over previous
#include <cuda_runtime.h>
#include <cuda_fp16.h>
#include <cstdint>

#define N_NODES 8192
#define D_FEAT  128
#define C_CLS   10
#define T_TRAIN 1024
#define ND (N_NODES * D_FEAT)

#define INV_SCALE (1.0f / 4096.0f)

// ---------------- scratch (device globals; no allocation allowed) ----------------
__device__ __align__(128) float  g_S[N_NODES * 256];     // [s_r|s_i] node-major [8192,256]
__device__ __align__(128) __half g_STh[256 * N_NODES];   // S^T fp16 [256,8192] K-major (GEMM B)
__device__ __align__(128) float  g_P[2 * N_NODES * 256]; // K-split partial sums
__device__ __align__(128) float  g_Msg[N_NODES * 256];   // combined msg [8192,256]
__device__ __align__(128) float  g_in[2 * N_NODES];      // in_r, in_i
__device__ __align__(128) float  g_pn[N_NODES * C_CLS];  // pseudo_norm
__device__ __align__(128) float  g_Wbig[256 * 256];      // [[Wr,-Wi],[Wi,Wr]] K-major

// ---------------- helpers ----------------
__device__ __forceinline__ void cp16(uint32_t smem, const void* g) {
    asm volatile("cp.async.cg.shared.global [%0], [%1], 16;\n" :: "r"(smem), "l"(g));
}
// exact x4096 via exponent add (adj >= 0; 0 stays ~0 after f16 round)
__device__ __forceinline__ uint32_t packh2_scaled(float x, float y) {
    float xs = __uint_as_float(__float_as_uint(x) + 0x06000000u);
    float ys = __uint_as_float(__float_as_uint(y) + 0x06000000u);
    __half2 h = __floats2half2_rn(xs, ys);
    return *reinterpret_cast<uint32_t*>(&h);
}

// ---------------- K0: build combined MLP weight ----------------
__global__ void k_build_wbig(const float* __restrict__ Wr, const float* __restrict__ Wi) {
    int idx = blockIdx.x * 256 + threadIdx.x;
    int d = idx >> 8, e = idx & 255;
    float v;
    if (d < 128) v = (e < 128) ? Wr[d * 128 + e] : -Wi[d * 128 + (e - 128)];
    else {
        int dd = d - 128;
        v = (e < 128) ? Wi[dd * 128 + e] : Wr[dd * 128 + (e - 128)];
    }
    g_Wbig[idx] = v;
}

// ---------------- K1: per-node prep ----------------
__global__ __launch_bounds__(256) void k_node_prep(
    const float* __restrict__ xr_g, const float* __restrict__ xi_g,
    const float* __restrict__ Wcr, const float* __restrict__ Wci,
    const float* __restrict__ bcr, const float* __restrict__ bci,
    const float* __restrict__ thr, const float* __restrict__ thi)
{
    __shared__ float sWr[C_CLS * 128], sWi[C_CLS * 128];
    __shared__ float sb[4 * C_CLS];
    int tid = threadIdx.x;
    for (int i = tid; i < C_CLS * 128; i += 256) { sWr[i] = Wcr[i]; sWi[i] = Wci[i]; }
    if (tid < C_CLS) {
        sb[tid] = bcr[tid]; sb[C_CLS + tid] = bci[tid];
        sb[2 * C_CLS + tid] = thr[tid]; sb[3 * C_CLS + tid] = thi[tid];
    }
    __syncthreads();

    int wid = tid >> 5, lane = tid & 31;
    int j = blockIdx.x * 8 + wid;

    float xr[4], xi[4];
#pragma unroll
    for (int k = 0; k < 4; k++) {
        xr[k] = xr_g[j * 128 + lane + 32 * k];
        xi[k] = xi_g[j * 128 + lane + 32 * k];
    }

    float pn[C_CLS];
#pragma unroll
    for (int c = 0; c < C_CLS; c++) {
        float p1 = 0.f, p2 = 0.f, p3 = 0.f, p4 = 0.f;
#pragma unroll
        for (int k = 0; k < 4; k++) {
            float wr = sWr[c * 128 + lane + 32 * k];
            float wi = sWi[c * 128 + lane + 32 * k];
            p1 += xr[k] * wr; p2 += xi[k] * wr;
            p3 += xi[k] * wi; p4 += xr[k] * wi;
        }
#pragma unroll
        for (int off = 16; off; off >>= 1) {
            p1 += __shfl_xor_sync(0xffffffffu, p1, off);
            p2 += __shfl_xor_sync(0xffffffffu, p2, off);
            p3 += __shfl_xor_sync(0xffffffffu, p3, off);
            p4 += __shfl_xor_sync(0xffffffffu, p4, off);
        }
        float cr = p1 + sb[c] - p3 - sb[C_CLS + c];
        float ci = p2 + sb[c] + p4 + sb[C_CLS + c];
        pn[c] = sqrtf(cr * cr + ci * ci);
    }

    float m = pn[0];
#pragma unroll
    for (int c = 1; c < C_CLS; c++) m = fmaxf(m, pn[c]);
    float s = 0.f, e[C_CLS];
#pragma unroll
    for (int c = 0; c < C_CLS; c++) { e[c] = expf(pn[c] - m); s += e[c]; }
    float inv = 1.0f / s, inr = 0.f, ini = 0.f;
#pragma unroll
    for (int c = 0; c < C_CLS; c++) {
        float sc = e[c] * inv;
        inr += sc * sb[2 * C_CLS + c];
        ini += sc * sb[3 * C_CLS + c];
    }

    if (lane == 0) {
#pragma unroll
        for (int c = 0; c < C_CLS; c++) g_pn[j * C_CLS + c] = pn[c];
        g_in[j] = inr; g_in[N_NODES + j] = ini;
    }

#pragma unroll
    for (int k = 0; k < 4; k++) {
        int d = lane + 32 * k;
        g_S[j * 256 + d]       = inr * xr[k] + ini * xi[k];
        g_S[j * 256 + 128 + d] = inr * xi[k] - ini * xr[k];
    }
}

// ---------------- K1b: transpose g_S [8192,256] f32 -> g_STh [256,8192] f16 ----------------
__global__ void k_transp() {
    __shared__ float t[32][33];
    int bx = blockIdx.x;
    int by = blockIdx.y;
    int lx = threadIdx.x, ly = threadIdx.y;
#pragma unroll
    for (int i = 0; i < 32; i += 8)
        t[ly + i][lx] = g_S[(size_t)(bx * 32 + ly + i) * 256 + by * 32 + lx];
    __syncthreads();
#pragma unroll
    for (int i = 0; i < 32; i += 8)
        g_STh[(size_t)(by * 32 + ly + i) * N_NODES + bx * 32 + lx] = __float2half(t[lx][ly + i]);
}

// ================= GEMM1: fp16 mma.sync, A converted to f16 in smem =================
// 128x256 CTA tile, 8 warps @ 64x64, A: LDG->cvt->STS (2-stage), B: cp.async (4-stage).
#define BM 128
#define BN 256
#define BK 32
#define NSPLIT 2
#define KSPLIT (N_NODES / NSPLIT)    // 4096
#define NKT (KSPLIT / BK)            // 128
#define ASTR 40                      // halfs per A smem row (80B)
#define BSTR 40                      // halfs per B smem row (80B)
#define ASTAGE (BM * ASTR)           // halfs/stage (A, 2 stages)
#define BSTAGE (BN * BSTR)           // halfs/stage (B, 4 stages)
#define SMEM_G1 ((2 * ASTAGE + 4 * BSTAGE) * 2)   // 102400 B

__global__ __launch_bounds__(256, 1) void k_gemm1(const float* __restrict__ adj) {
    extern __shared__ __align__(16) char smraw[];
    __half* Ah = reinterpret_cast<__half*>(smraw);
    __half* Bs = reinterpret_cast<__half*>(smraw + 2 * ASTAGE * 2);

    int tid = threadIdx.x;
    int m0 = blockIdx.x * BM;
    int kb = blockIdx.z * KSPLIT;
    const float*  Ag = adj + (size_t)m0 * N_NODES + kb;
    const __half* Bg = g_STh + kb;

    uint32_t sB = (uint32_t)__cvta_generic_to_shared(Bs);

    // A: thread t handles row r=t>>1, 16 cols starting at (t&1)*16
    int ar = tid >> 1, ac = (tid & 1) * 16;
    const float4* Arow = reinterpret_cast<const float4*>(Ag + (size_t)ar * N_NODES + ac);

    float4 pa[4];
    auto ldgA = [&](int kt) {
        const float4* p = reinterpret_cast<const float4*>(
            Ag + (size_t)ar * N_NODES + kt * BK + ac);
#pragma unroll
        for (int i = 0; i < 4; i++) pa[i] = p[i];
    };
    auto stsA = [&](int st) {
        uint32_t d[8];
#pragma unroll
        for (int i = 0; i < 4; i++) {
            d[2 * i]     = packh2_scaled(pa[i].x, pa[i].y);
            d[2 * i + 1] = packh2_scaled(pa[i].z, pa[i].w);
        }
        uint4* dst = reinterpret_cast<uint4*>(Ah + st * ASTAGE + ar * ASTR + ac);
        dst[0] = make_uint4(d[0], d[1], d[2], d[3]);
        dst[1] = make_uint4(d[4], d[5], d[6], d[7]);
    };

    auto loadB = [&](int kt) {
        int st = kt & 3;
        int k0 = kt * BK;
#pragma unroll
        for (int i = 0; i < 4; i++) {               // 1024 vec16 / 256 thr
            int v = tid + i * 256;
            int r = v >> 2, c = v & 3;
            cp16(sB + (uint32_t)(st * BSTAGE + r * BSTR + c * 8) * 2,
                 Bg + (size_t)r * N_NODES + k0 + c * 8);
        }
        asm volatile("cp.async.commit_group;\n");
    };

    float acc[4][8][4];
#pragma unroll
    for (int a = 0; a < 4; a++)
#pragma unroll
        for (int b = 0; b < 8; b++)
#pragma unroll
            for (int c = 0; c < 4; c++) acc[a][b][c] = 0.f;

    int wid = tid >> 5, lane = tid & 31;
    int wm = (wid & 1) * 64;        // warp grid 2(m) x 4(n), warp tile 64x64
    int wn = (wid >> 1) * 64;
    int g = lane >> 2, tg = lane & 3;

    ldgA(0);
    loadB(0); loadB(1); loadB(2);

    for (int kt = 0; kt < NKT; kt++) {
        stsA(kt & 1);
        if (kt + 1 < NKT) ldgA(kt + 1);

        // wait for B(kt): pending groups are {kt..min(kt+2, NKT-1)}
        int rem = NKT - 1 - kt;
        if (rem >= 2)      asm volatile("cp.async.wait_group 2;\n");
        else if (rem == 1) asm volatile("cp.async.wait_group 1;\n");
        else               asm volatile("cp.async.wait_group 0;\n");
        __syncthreads();
        if (kt + 3 < NKT) loadB(kt + 3);

        const __half* as = Ah + (kt & 1) * ASTAGE;
        const __half* bs = Bs + (kt & 3) * BSTAGE;
#pragma unroll
        for (int kk = 0; kk < 2; kk++) {
            int k0 = kk * 16;
            uint32_t a[4][4], b[8][2];
#pragma unroll
            for (int mf = 0; mf < 4; mf++) {
                int rb = wm + mf * 16;
                const __half* p0 = as + (rb + g) * ASTR + k0 + 2 * tg;
                const __half* p1 = p0 + 8 * ASTR;
                a[mf][0] = *reinterpret_cast<const uint32_t*>(p0);
                a[mf][1] = *reinterpret_cast<const uint32_t*>(p1);
                a[mf][2] = *reinterpret_cast<const uint32_t*>(p0 + 8);
                a[mf][3] = *reinterpret_cast<const uint32_t*>(p1 + 8);
            }
#pragma unroll
            for (int nf = 0; nf < 8; nf++) {
                int nr = wn + nf * 8 + g;
                b[nf][0] = *reinterpret_cast<const uint32_t*>(bs + nr * BSTR + k0 + 2 * tg);
                b[nf][1] = *reinterpret_cast<const uint32_t*>(bs + nr * BSTR + k0 + 2 * tg + 8);
            }
#pragma unroll
            for (int nf = 0; nf < 8; nf++)
#pragma unroll
                for (int mf = 0; mf < 4; mf++) {
                    asm volatile(
                        "mma.sync.aligned.m16n8k16.row.col.f32.f16.f16.f32 "
                        "{%0,%1,%2,%3}, {%4,%5,%6,%7}, {%8,%9}, {%0,%1,%2,%3};\n"
                        : "+f"(acc[mf][nf][0]), "+f"(acc[mf][nf][1]),
                          "+f"(acc[mf][nf][2]), "+f"(acc[mf][nf][3])
                        : "r"(a[mf][0]), "r"(a[mf][1]), "r"(a[mf][2]), "r"(a[mf][3]),
                          "r"(b[nf][0]), "r"(b[nf][1]));
                }
        }
        __syncthreads();
    }

    // epilogue: raw partial store
    float* P = g_P + (size_t)blockIdx.z * (N_NODES * 256);
#pragma unroll
    for (int mf = 0; mf < 4; mf++)
#pragma unroll
        for (int nf = 0; nf < 8; nf++) {
            int row = m0 + wm + mf * 16 + g;
            int col = wn + nf * 8 + 2 * tg;
            P[(size_t)row * 256 + col]           = acc[mf][nf][0];
            P[(size_t)row * 256 + col + 1]       = acc[mf][nf][1];
            P[(size_t)(row + 8) * 256 + col]     = acc[mf][nf][2];
            P[(size_t)(row + 8) * 256 + col + 1] = acc[mf][nf][3];
        }
}

// ---------------- K2b: msg = diag(in) * (P0 + P1) / SCALE ----------------
__global__ void k_combine2() {
    int t = blockIdx.x * 256 + threadIdx.x;
    int n = t >> 7, d = t & 127;
    size_t b = (size_t)n * 256;
    const size_t PS = (size_t)N_NODES * 256;
    float mr = (g_P[b + d]       + g_P[PS + b + d])       * INV_SCALE;
    float mi = (g_P[b + 128 + d] + g_P[PS + b + 128 + d]) * INV_SCALE;
    float inr = g_in[n], ini = g_in[N_NODES + n];
    g_Msg[b + d]       = inr * mr - ini * mi;
    g_Msg[b + 128 + d] = inr * mi + ini * mr;
}

// ---------------- K3: MLP GEMM (tf32, fused bias+residual+split) ----------------
#define KT   16
#define SROW 20

__global__ __launch_bounds__(256) void k_gemm_mlp(
    const float* __restrict__ br, const float* __restrict__ bi,
    const float* __restrict__ xr, const float* __restrict__ xi,
    float* __restrict__ out)
{
    __shared__ __align__(16) float As2[2][128 * SROW];
    __shared__ __align__(16) float Bs2[2][128 * SROW];

    const float* A = g_Msg; const float* B = g_Wbig;
    const int lda = 256, ldb = 256, nk = 256 / KT;

    int tid = threadIdx.x;
    int m0 = blockIdx.x * 128;
    int n0 = blockIdx.y * 128;
    const float* Ag = A + (size_t)m0 * lda;
    const float* Bg = B + (size_t)n0 * ldb;

    uint32_t sA = (uint32_t)__cvta_generic_to_shared(&As2[0][0]);
    uint32_t sB = (uint32_t)__cvta_generic_to_shared(&Bs2[0][0]);

    auto load_stage = [&](int buf, int kt) {
        int k0 = kt * KT;
#pragma unroll
        for (int i = 0; i < 2; i++) {
            int v = tid + i * 256;
            int r = v >> 2, c4 = v & 3;
            cp16(sA + (uint32_t)(buf * 128 * SROW + r * SROW + c4 * 4) * 4,
                 Ag + (size_t)r * lda + k0 + c4 * 4);
            cp16(sB + (uint32_t)(buf * 128 * SROW + r * SROW + c4 * 4) * 4,
                 Bg + (size_t)r * ldb + k0 + c4 * 4);
        }
        asm volatile("cp.async.commit_group;\n");
    };

    float acc[2][8][4];
#pragma unroll
    for (int a = 0; a < 2; a++)
#pragma unroll
        for (int b = 0; b < 8; b++)
#pragma unroll
            for (int c = 0; c < 4; c++) acc[a][b][c] = 0.f;

    int wid = tid >> 5, lane = tid & 31;
    int wm = (wid & 3) * 32;
    int wn = (wid >> 2) * 64;
    int g = lane >> 2, tg = lane & 3;

    load_stage(0, 0);
    for (int kt = 0; kt < nk; kt++) {
        if (kt + 1 < nk) {
            load_stage((kt + 1) & 1, kt + 1);
            asm volatile("cp.async.wait_group 1;\n");
        } else {
            asm volatile("cp.async.wait_group 0;\n");
        }
        __syncthreads();
        const float* as = &As2[kt & 1][0];
        const float* bs = &Bs2[kt & 1][0];
#pragma unroll
        for (int k8 = 0; k8 < 2; k8++) {
            uint32_t a[2][4], b[8][2];
#pragma unroll
            for (int mf = 0; mf < 2; mf++) {
                int rb = wm + mf * 16;
                a[mf][0] = __float_as_uint(as[(rb + g)     * SROW + k8 * 8 + tg]);
                a[mf][1] = __float_as_uint(as[(rb + g + 8) * SROW + k8 * 8 + tg]);
                a[mf][2] = __float_as_uint(as[(rb + g)     * SROW + k8 * 8 + tg + 4]);
                a[mf][3] = __float_as_uint(as[(rb + g + 8) * SROW + k8 * 8 + tg + 4]);
            }
#pragma unroll
            for (int nf = 0; nf < 8; nf++) {
                int cb = wn + nf * 8;
                b[nf][0] = __float_as_uint(bs[(cb + g) * SROW + k8 * 8 + tg]);
                b[nf][1] = __float_as_uint(bs[(cb + g) * SROW + k8 * 8 + tg + 4]);
            }
#pragma unroll
            for (int mf = 0; mf < 2; mf++)
#pragma unroll
                for (int nf = 0; nf < 8; nf++) {
                    asm volatile(
                        "mma.sync.aligned.m16n8k8.row.col.f32.tf32.tf32.f32 "
                        "{%0,%1,%2,%3}, {%4,%5,%6,%7}, {%8,%9}, {%0,%1,%2,%3};\n"
                        : "+f"(acc[mf][nf][0]), "+f"(acc[mf][nf][1]),
                          "+f"(acc[mf][nf][2]), "+f"(acc[mf][nf][3])
                        : "r"(a[mf][0]), "r"(a[mf][1]), "r"(a[mf][2]), "r"(a[mf][3]),
                          "r"(b[nf][0]), "r"(b[nf][1]));
                }
        }
        __syncthreads();
    }

#pragma unroll
    for (int mf = 0; mf < 2; mf++)
#pragma unroll
        for (int nf = 0; nf < 8; nf++) {
            int row = m0 + wm + mf * 16 + g;
            int col = n0 + wn + nf * 8 + 2 * tg;
#pragma unroll
            for (int q = 0; q < 4; q++) {
                int r = row + (q >> 1) * 8;
                int c = col + (q & 1);
                float v = acc[mf][nf][q];
                if (c < 128) {
                    out[(size_t)r * 128 + c] =
                        v + br[c] - bi[c] + xr[(size_t)r * 128 + c];
                } else {
                    int cc = c - 128;
                    out[(size_t)ND + (size_t)r * 128 + cc] =
                        v + br[cc] + bi[cc] + xi[(size_t)r * 128 + cc];
                }
            }
        }
}

// ---------------- K4: losses ----------------
__global__ void k_losses(const float* __restrict__ thi,
                         const int* __restrict__ labels,
                         const int* __restrict__ tidx,
                         float* __restrict__ out)
{
    __shared__ float red[256];
    int tid = threadIdx.x;

    if (tid == 0) {
        float st[C_CLS];
        for (int c = 0; c < C_CLS; c++) st[c] = thi[c];
        for (int i = 1; i < C_CLS; i++) {
            float key = st[i]; int k = i - 1;
            while (k >= 0 && st[k] > key) { st[k + 1] = st[k]; k--; }
            st[k + 1] = key;
        }
        float sum = 0.f, mx = 0.f;
        for (int c = 0; c < C_CLS - 1; c++) {
            float d = fabsf(st[c + 1] - st[c]);
            sum += d; if (d > mx) mx = d;
        }
        float difference = sum / (mx + 1e-6f);
        out[(size_t)2 * ND] = 0.1f / (1e-6f + difference);
    }

    float accn = 0.f;
    for (int t = tid; t < T_TRAIN; t += 256) {
        int row = tidx[t];
        int lab = labels[row];
        float l[C_CLS]; float m = -1e30f;
#pragma unroll
        for (int c = 0; c < C_CLS; c++) { l[c] = g_pn[row * C_CLS + c]; m = fmaxf(m, l[c]); }
        float s = 0.f;
#pragma unroll
        for (int c = 0; c < C_CLS; c++) s += expf(l[c] - m);
        float lse = m + logf(s);
        float lp = 0.f;
#pragma unroll
        for (int c = 0; c < C_CLS; c++) if (c == lab) lp = l[c] - lse;
        accn += -lp;
    }
    red[tid] = accn;
    __syncthreads();
    for (int off = 128; off; off >>= 1) {
        if (tid < off) red[tid] += red[tid + off];
        __syncthreads();
    }
    if (tid == 0) out[(size_t)2 * ND + 1] = red[0] / (float)T_TRAIN * 0.1f;
}

// ---------------- launch ----------------
extern "C" void kernel_launch(void* const* d_in, const int* in_sizes, int n_in,
                              void* d_out, int out_size)
{
    const float* x_real     = (const float*)d_in[0];
    const float* x_imag     = (const float*)d_in[1];
    const float* adj        = (const float*)d_in[2];
    const float* theta_real = (const float*)d_in[3];
    const float* theta_imag = (const float*)d_in[4];
    const float* W_r        = (const float*)d_in[5];
    const float* b_r        = (const float*)d_in[6];
    const float* W_i        = (const float*)d_in[7];
    const float* b_i        = (const float*)d_in[8];
    const float* Wc_r       = (const float*)d_in[9];
    const float* bc_r       = (const float*)d_in[10];
    const float* Wc_i       = (const float*)d_in[11];
    const float* bc_i       = (const float*)d_in[12];
    const int*   labels     = (const int*)d_in[13];
    const int*   train_idx  = (const int*)d_in[14];
    float* out = (float*)d_out;

    cudaFuncSetAttribute(k_gemm1, cudaFuncAttributeMaxDynamicSharedMemorySize, SMEM_G1);

    k_build_wbig<<<256, 256>>>(W_r, W_i);
    k_node_prep<<<1024, 256>>>(x_real, x_imag, Wc_r, Wc_i, bc_r, bc_i,
                               theta_real, theta_imag);
    k_transp<<<dim3(256, 8), dim3(32, 8)>>>();
    k_gemm1<<<dim3(64, 1, NSPLIT), 256, SMEM_G1>>>(adj);
    k_combine2<<<4096, 256>>>();
    k_gemm_mlp<<<dim3(64, 2), 256>>>(b_r, b_i, x_real, x_imag, out);
    k_losses<<<1, 256>>>(theta_imag, labels, train_idx, out);
}

// round 10
// speedup vs baseline: 1.0829x; 1.0590x over previous
#include <cuda_runtime.h>
#include <cuda_fp16.h>
#include <cstdint>

#define N_NODES 8192
#define D_FEAT  128
#define C_CLS   10
#define T_TRAIN 1024
#define ND (N_NODES * D_FEAT)

#define INV_SCALE (1.0f / 4096.0f)

// ---------------- scratch (device globals; no allocation allowed) ----------------
__device__ __align__(128) float  g_S[N_NODES * 256];     // [s_r|s_i] node-major [8192,256]
__device__ __align__(128) __half g_STh[256 * N_NODES];   // S^T fp16 [256,8192] K-major (GEMM B)
__device__ __align__(128) float  g_P[2 * N_NODES * 256]; // K-split partial sums
__device__ __align__(128) float  g_Msg[N_NODES * 256];   // combined msg [8192,256]
__device__ __align__(128) float  g_in[2 * N_NODES];      // in_r, in_i
__device__ __align__(128) float  g_pn[N_NODES * C_CLS];  // pseudo_norm
__device__ __align__(128) float  g_Wbig[256 * 256];      // [[Wr,-Wi],[Wi,Wr]] K-major

// ---------------- helpers ----------------
__device__ __forceinline__ void cp16(uint32_t smem, const void* g) {
    asm volatile("cp.async.cg.shared.global [%0], [%1], 16;\n" :: "r"(smem), "l"(g));
}
// exact x4096 via exponent add (adj >= 0; 0 stays ~0 after f16 round)
__device__ __forceinline__ uint32_t packh2_scaled(float x, float y) {
    float xs = __uint_as_float(__float_as_uint(x) + 0x06000000u);
    float ys = __uint_as_float(__float_as_uint(y) + 0x06000000u);
    __half2 h = __floats2half2_rn(xs, ys);
    return *reinterpret_cast<uint32_t*>(&h);
}
#define LDSM_X4(r0, r1, r2, r3, addr) \
    asm volatile("ldmatrix.sync.aligned.m8n8.x4.shared.b16 {%0,%1,%2,%3}, [%4];" \
        : "=r"(r0), "=r"(r1), "=r"(r2), "=r"(r3) : "r"(addr))

// ---------------- K0: build combined MLP weight ----------------
__global__ void k_build_wbig(const float* __restrict__ Wr, const float* __restrict__ Wi) {
    int idx = blockIdx.x * 256 + threadIdx.x;
    int d = idx >> 8, e = idx & 255;
    float v;
    if (d < 128) v = (e < 128) ? Wr[d * 128 + e] : -Wi[d * 128 + (e - 128)];
    else {
        int dd = d - 128;
        v = (e < 128) ? Wi[dd * 128 + e] : Wr[dd * 128 + (e - 128)];
    }
    g_Wbig[idx] = v;
}

// ---------------- K1: per-node prep ----------------
__global__ __launch_bounds__(256) void k_node_prep(
    const float* __restrict__ xr_g, const float* __restrict__ xi_g,
    const float* __restrict__ Wcr, const float* __restrict__ Wci,
    const float* __restrict__ bcr, const float* __restrict__ bci,
    const float* __restrict__ thr, const float* __restrict__ thi)
{
    __shared__ float sWr[C_CLS * 128], sWi[C_CLS * 128];
    __shared__ float sb[4 * C_CLS];
    int tid = threadIdx.x;
    for (int i = tid; i < C_CLS * 128; i += 256) { sWr[i] = Wcr[i]; sWi[i] = Wci[i]; }
    if (tid < C_CLS) {
        sb[tid] = bcr[tid]; sb[C_CLS + tid] = bci[tid];
        sb[2 * C_CLS + tid] = thr[tid]; sb[3 * C_CLS + tid] = thi[tid];
    }
    __syncthreads();

    int wid = tid >> 5, lane = tid & 31;
    int j = blockIdx.x * 8 + wid;

    float xr[4], xi[4];
#pragma unroll
    for (int k = 0; k < 4; k++) {
        xr[k] = xr_g[j * 128 + lane + 32 * k];
        xi[k] = xi_g[j * 128 + lane + 32 * k];
    }

    float pn[C_CLS];
#pragma unroll
    for (int c = 0; c < C_CLS; c++) {
        float p1 = 0.f, p2 = 0.f, p3 = 0.f, p4 = 0.f;
#pragma unroll
        for (int k = 0; k < 4; k++) {
            float wr = sWr[c * 128 + lane + 32 * k];
            float wi = sWi[c * 128 + lane + 32 * k];
            p1 += xr[k] * wr; p2 += xi[k] * wr;
            p3 += xi[k] * wi; p4 += xr[k] * wi;
        }
#pragma unroll
        for (int off = 16; off; off >>= 1) {
            p1 += __shfl_xor_sync(0xffffffffu, p1, off);
            p2 += __shfl_xor_sync(0xffffffffu, p2, off);
            p3 += __shfl_xor_sync(0xffffffffu, p3, off);
            p4 += __shfl_xor_sync(0xffffffffu, p4, off);
        }
        float cr = p1 + sb[c] - p3 - sb[C_CLS + c];
        float ci = p2 + sb[c] + p4 + sb[C_CLS + c];
        pn[c] = sqrtf(cr * cr + ci * ci);
    }

    float m = pn[0];
#pragma unroll
    for (int c = 1; c < C_CLS; c++) m = fmaxf(m, pn[c]);
    float s = 0.f, e[C_CLS];
#pragma unroll
    for (int c = 0; c < C_CLS; c++) { e[c] = expf(pn[c] - m); s += e[c]; }
    float inv = 1.0f / s, inr = 0.f, ini = 0.f;
#pragma unroll
    for (int c = 0; c < C_CLS; c++) {
        float sc = e[c] * inv;
        inr += sc * sb[2 * C_CLS + c];
        ini += sc * sb[3 * C_CLS + c];
    }

    if (lane == 0) {
#pragma unroll
        for (int c = 0; c < C_CLS; c++) g_pn[j * C_CLS + c] = pn[c];
        g_in[j] = inr; g_in[N_NODES + j] = ini;
    }

#pragma unroll
    for (int k = 0; k < 4; k++) {
        int d = lane + 32 * k;
        g_S[j * 256 + d]       = inr * xr[k] + ini * xi[k];
        g_S[j * 256 + 128 + d] = inr * xi[k] - ini * xr[k];
    }
}

// ---------------- K1b: transpose g_S [8192,256] f32 -> g_STh [256,8192] f16 ----------------
__global__ void k_transp() {
    __shared__ float t[32][33];
    int bx = blockIdx.x;
    int by = blockIdx.y;
    int lx = threadIdx.x, ly = threadIdx.y;
#pragma unroll
    for (int i = 0; i < 32; i += 8)
        t[ly + i][lx] = g_S[(size_t)(bx * 32 + ly + i) * 256 + by * 32 + lx];
    __syncthreads();
#pragma unroll
    for (int i = 0; i < 32; i += 8)
        g_STh[(size_t)(by * 32 + ly + i) * N_NODES + bx * 32 + lx] = __float2half(t[lx][ly + i]);
}

// ================= GEMM1: fp16 mma.sync + ldmatrix + fragment DB =================
// 128x256 CTA tile, 8 warps @ 64x64, A: LDG->cvt->STS (2-stage), B: cp.async (4-stage).
#define BM 128
#define BN 256
#define BK 32
#define NSPLIT 2
#define KSPLIT (N_NODES / NSPLIT)    // 4096
#define NKT (KSPLIT / BK)            // 128
#define ASTR 40                      // halfs per A smem row (80B)
#define BSTR 40                      // halfs per B smem row (80B)
#define ASTAGE (BM * ASTR)           // halfs/stage (A, 2 stages)
#define BSTAGE (BN * BSTR)           // halfs/stage (B, 4 stages)
#define SMEM_G1 ((2 * ASTAGE + 4 * BSTAGE) * 2)   // 102400 B

__global__ __launch_bounds__(256, 1) void k_gemm1(const float* __restrict__ adj) {
    extern __shared__ __align__(16) char smraw[];
    __half* Ah = reinterpret_cast<__half*>(smraw);
    __half* Bs = reinterpret_cast<__half*>(smraw + 2 * ASTAGE * 2);

    int tid = threadIdx.x;
    int m0 = blockIdx.x * BM;
    int kb = blockIdx.z * KSPLIT;
    const float*  Ag = adj + (size_t)m0 * N_NODES + kb;
    const __half* Bg = g_STh + kb;

    uint32_t sAh = (uint32_t)__cvta_generic_to_shared(Ah);
    uint32_t sB  = (uint32_t)__cvta_generic_to_shared(Bs);

    // A: thread t handles row r=t>>1, 16 cols starting at (t&1)*16
    int ar = tid >> 1, ac = (tid & 1) * 16;

    float4 pa[4];
    auto ldgA = [&](int kt) {
        const float4* p = reinterpret_cast<const float4*>(
            Ag + (size_t)ar * N_NODES + kt * BK + ac);
#pragma unroll
        for (int i = 0; i < 4; i++) pa[i] = p[i];
    };
    auto stsA = [&](int st) {
        uint32_t d[8];
#pragma unroll
        for (int i = 0; i < 4; i++) {
            d[2 * i]     = packh2_scaled(pa[i].x, pa[i].y);
            d[2 * i + 1] = packh2_scaled(pa[i].z, pa[i].w);
        }
        uint4* dst = reinterpret_cast<uint4*>(Ah + st * ASTAGE + ar * ASTR + ac);
        dst[0] = make_uint4(d[0], d[1], d[2], d[3]);
        dst[1] = make_uint4(d[4], d[5], d[6], d[7]);
    };

    auto loadB = [&](int kt) {
        int st = kt & 3;
        int k0 = kt * BK;
#pragma unroll
        for (int i = 0; i < 4; i++) {               // 1024 vec16 / 256 thr
            int v = tid + i * 256;
            int r = v >> 2, c = v & 3;
            cp16(sB + (uint32_t)(st * BSTAGE + r * BSTR + c * 8) * 2,
                 Bg + (size_t)r * N_NODES + k0 + c * 8);
        }
        asm volatile("cp.async.commit_group;\n");
    };

    float acc[4][8][4];
#pragma unroll
    for (int a = 0; a < 4; a++)
#pragma unroll
        for (int b = 0; b < 8; b++)
#pragma unroll
            for (int c = 0; c < 4; c++) acc[a][b][c] = 0.f;

    int wid = tid >> 5, lane = tid & 31;
    int wm = (wid & 1) * 64;        // warp grid 2(m) x 4(n), warp tile 64x64
    int wn = (wid >> 1) * 64;

    uint32_t Af[2][16], Bf[2][16];

    // LDSM lane addressing (fixed per thread, add stage/k0 offsets later)
    int a_row = lane & 15, a_half = (lane >> 4) * 8;                 // A: 16 rows x2 halves
    int b_q = lane >> 3, b_r = lane & 7;                             // B: 4 quads of 8 rows
    int b_nfo = (b_q >> 1), b_half = (b_q & 1) * 8;

    auto fragload = [&](int buf, int ast, int bst, int k0) {
#pragma unroll
        for (int mf = 0; mf < 4; mf++) {
            uint32_t ad = sAh + (uint32_t)(ast * ASTAGE +
                (wm + mf * 16 + a_row) * ASTR + k0 + a_half) * 2;
            LDSM_X4(Af[buf][mf * 4 + 0], Af[buf][mf * 4 + 1],
                    Af[buf][mf * 4 + 2], Af[buf][mf * 4 + 3], ad);
        }
#pragma unroll
        for (int p = 0; p < 4; p++) {
            int nf = p * 2 + b_nfo;
            uint32_t ad = sB + (uint32_t)(bst * BSTAGE +
                (wn + nf * 8 + b_r) * BSTR + k0 + b_half) * 2;
            LDSM_X4(Bf[buf][p * 4 + 0], Bf[buf][p * 4 + 1],
                    Bf[buf][p * 4 + 2], Bf[buf][p * 4 + 3], ad);
        }
    };

    auto mma_all = [&](int buf) {
#pragma unroll
        for (int nf = 0; nf < 8; nf++) {
            uint32_t b0 = Bf[buf][(nf >> 1) * 4 + (nf & 1) * 2];
            uint32_t b1 = Bf[buf][(nf >> 1) * 4 + (nf & 1) * 2 + 1];
#pragma unroll
            for (int mf = 0; mf < 4; mf++) {
                asm volatile(
                    "mma.sync.aligned.m16n8k16.row.col.f32.f16.f16.f32 "
                    "{%0,%1,%2,%3}, {%4,%5,%6,%7}, {%8,%9}, {%0,%1,%2,%3};\n"
                    : "+f"(acc[mf][nf][0]), "+f"(acc[mf][nf][1]),
                      "+f"(acc[mf][nf][2]), "+f"(acc[mf][nf][3])
                    : "r"(Af[buf][mf * 4 + 0]), "r"(Af[buf][mf * 4 + 1]),
                      "r"(Af[buf][mf * 4 + 2]), "r"(Af[buf][mf * 4 + 3]),
                      "r"(b0), "r"(b1));
            }
        }
    };

    // prologue
    ldgA(0);
    loadB(0); loadB(1); loadB(2);
    stsA(0);
    ldgA(1);
    asm volatile("cp.async.wait_group 2;\n");
    __syncthreads();

    for (int kt = 0; kt < NKT; kt++) {
        if (kt + 3 < NKT) loadB(kt + 3);
        fragload(0, kt & 1, kt & 3, 0);
        fragload(1, kt & 1, kt & 3, 16);
        mma_all(0);
        if (kt + 1 < NKT) {
            stsA((kt + 1) & 1);
            if (kt + 2 < NKT) ldgA(kt + 2);
        }
        mma_all(1);
        if (kt + 1 < NKT) {
            int rem = NKT - 2 - kt;
            if (rem >= 2)      asm volatile("cp.async.wait_group 2;\n");
            else if (rem == 1) asm volatile("cp.async.wait_group 1;\n");
            else               asm volatile("cp.async.wait_group 0;\n");
            __syncthreads();
        }
    }

    // epilogue: raw partial store
    int g = lane >> 2, tg = lane & 3;
    float* P = g_P + (size_t)blockIdx.z * (N_NODES * 256);
#pragma unroll
    for (int mf = 0; mf < 4; mf++)
#pragma unroll
        for (int nf = 0; nf < 8; nf++) {
            int row = m0 + wm + mf * 16 + g;
            int col = wn + nf * 8 + 2 * tg;
            P[(size_t)row * 256 + col]           = acc[mf][nf][0];
            P[(size_t)row * 256 + col + 1]       = acc[mf][nf][1];
            P[(size_t)(row + 8) * 256 + col]     = acc[mf][nf][2];
            P[(size_t)(row + 8) * 256 + col + 1] = acc[mf][nf][3];
        }
}

// ---------------- K2b: msg = diag(in) * (P0 + P1) / SCALE ----------------
__global__ void k_combine2() {
    int t = blockIdx.x * 256 + threadIdx.x;
    int n = t >> 7, d = t & 127;
    size_t b = (size_t)n * 256;
    const size_t PS = (size_t)N_NODES * 256;
    float mr = (g_P[b + d]       + g_P[PS + b + d])       * INV_SCALE;
    float mi = (g_P[b + 128 + d] + g_P[PS + b + 128 + d]) * INV_SCALE;
    float inr = g_in[n], ini = g_in[N_NODES + n];
    g_Msg[b + d]       = inr * mr - ini * mi;
    g_Msg[b + 128 + d] = inr * mi + ini * mr;
}

// ---------------- K3: MLP GEMM (tf32, fused bias+residual+split) ----------------
#define KT   16
#define SROW 20

__global__ __launch_bounds__(256) void k_gemm_mlp(
    const float* __restrict__ br, const float* __restrict__ bi,
    const float* __restrict__ xr, const float* __restrict__ xi,
    float* __restrict__ out)
{
    __shared__ __align__(16) float As2[2][128 * SROW];
    __shared__ __align__(16) float Bs2[2][128 * SROW];

    const float* A = g_Msg; const float* B = g_Wbig;
    const int lda = 256, ldb = 256, nk = 256 / KT;

    int tid = threadIdx.x;
    int m0 = blockIdx.x * 128;
    int n0 = blockIdx.y * 128;
    const float* Ag = A + (size_t)m0 * lda;
    const float* Bg = B + (size_t)n0 * ldb;

    uint32_t sA = (uint32_t)__cvta_generic_to_shared(&As2[0][0]);
    uint32_t sB = (uint32_t)__cvta_generic_to_shared(&Bs2[0][0]);

    auto load_stage = [&](int buf, int kt) {
        int k0 = kt * KT;
#pragma unroll
        for (int i = 0; i < 2; i++) {
            int v = tid + i * 256;
            int r = v >> 2, c4 = v & 3;
            cp16(sA + (uint32_t)(buf * 128 * SROW + r * SROW + c4 * 4) * 4,
                 Ag + (size_t)r * lda + k0 + c4 * 4);
            cp16(sB + (uint32_t)(buf * 128 * SROW + r * SROW + c4 * 4) * 4,
                 Bg + (size_t)r * ldb + k0 + c4 * 4);
        }
        asm volatile("cp.async.commit_group;\n");
    };

    float acc[2][8][4];
#pragma unroll
    for (int a = 0; a < 2; a++)
#pragma unroll
        for (int b = 0; b < 8; b++)
#pragma unroll
            for (int c = 0; c < 4; c++) acc[a][b][c] = 0.f;

    int wid = tid >> 5, lane = tid & 31;
    int wm = (wid & 3) * 32;
    int wn = (wid >> 2) * 64;
    int g = lane >> 2, tg = lane & 3;

    load_stage(0, 0);
    for (int kt = 0; kt < nk; kt++) {
        if (kt + 1 < nk) {
            load_stage((kt + 1) & 1, kt + 1);
            asm volatile("cp.async.wait_group 1;\n");
        } else {
            asm volatile("cp.async.wait_group 0;\n");
        }
        __syncthreads();
        const float* as = &As2[kt & 1][0];
        const float* bs = &Bs2[kt & 1][0];
#pragma unroll
        for (int k8 = 0; k8 < 2; k8++) {
            uint32_t a[2][4], b[8][2];
#pragma unroll
            for (int mf = 0; mf < 2; mf++) {
                int rb = wm + mf * 16;
                a[mf][0] = __float_as_uint(as[(rb + g)     * SROW + k8 * 8 + tg]);
                a[mf][1] = __float_as_uint(as[(rb + g + 8) * SROW + k8 * 8 + tg]);
                a[mf][2] = __float_as_uint(as[(rb + g)     * SROW + k8 * 8 + tg + 4]);
                a[mf][3] = __float_as_uint(as[(rb + g + 8) * SROW + k8 * 8 + tg + 4]);
            }
#pragma unroll
            for (int nf = 0; nf < 8; nf++) {
                int cb = wn + nf * 8;
                b[nf][0] = __float_as_uint(bs[(cb + g) * SROW + k8 * 8 + tg]);
                b[nf][1] = __float_as_uint(bs[(cb + g) * SROW + k8 * 8 + tg + 4]);
            }
#pragma unroll
            for (int mf = 0; mf < 2; mf++)
#pragma unroll
                for (int nf = 0; nf < 8; nf++) {
                    asm volatile(
                        "mma.sync.aligned.m16n8k8.row.col.f32.tf32.tf32.f32 "
                        "{%0,%1,%2,%3}, {%4,%5,%6,%7}, {%8,%9}, {%0,%1,%2,%3};\n"
                        : "+f"(acc[mf][nf][0]), "+f"(acc[mf][nf][1]),
                          "+f"(acc[mf][nf][2]), "+f"(acc[mf][nf][3])
                        : "r"(a[mf][0]), "r"(a[mf][1]), "r"(a[mf][2]), "r"(a[mf][3]),
                          "r"(b[nf][0]), "r"(b[nf][1]));
                }
        }
        __syncthreads();
    }

#pragma unroll
    for (int mf = 0; mf < 2; mf++)
#pragma unroll
        for (int nf = 0; nf < 8; nf++) {
            int row = m0 + wm + mf * 16 + g;
            int col = n0 + wn + nf * 8 + 2 * tg;
#pragma unroll
            for (int q = 0; q < 4; q++) {
                int r = row + (q >> 1) * 8;
                int c = col + (q & 1);
                float v = acc[mf][nf][q];
                if (c < 128) {
                    out[(size_t)r * 128 + c] =
                        v + br[c] - bi[c] + xr[(size_t)r * 128 + c];
                } else {
                    int cc = c - 128;
                    out[(size_t)ND + (size_t)r * 128 + cc] =
                        v + br[cc] + bi[cc] + xi[(size_t)r * 128 + cc];
                }
            }
        }
}

// ---------------- K4: losses ----------------
__global__ void k_losses(const float* __restrict__ thi,
                         const int* __restrict__ labels,
                         const int* __restrict__ tidx,
                         float* __restrict__ out)
{
    __shared__ float red[256];
    int tid = threadIdx.x;

    if (tid == 0) {
        float st[C_CLS];
        for (int c = 0; c < C_CLS; c++) st[c] = thi[c];
        for (int i = 1; i < C_CLS; i++) {
            float key = st[i]; int k = i - 1;
            while (k >= 0 && st[k] > key) { st[k + 1] = st[k]; k--; }
            st[k + 1] = key;
        }
        float sum = 0.f, mx = 0.f;
        for (int c = 0; c < C_CLS - 1; c++) {
            float d = fabsf(st[c + 1] - st[c]);
            sum += d; if (d > mx) mx = d;
        }
        float difference = sum / (mx + 1e-6f);
        out[(size_t)2 * ND] = 0.1f / (1e-6f + difference);
    }

    float accn = 0.f;
    for (int t = tid; t < T_TRAIN; t += 256) {
        int row = tidx[t];
        int lab = labels[row];
        float l[C_CLS]; float m = -1e30f;
#pragma unroll
        for (int c = 0; c < C_CLS; c++) { l[c] = g_pn[row * C_CLS + c]; m = fmaxf(m, l[c]); }
        float s = 0.f;
#pragma unroll
        for (int c = 0; c < C_CLS; c++) s += expf(l[c] - m);
        float lse = m + logf(s);
        float lp = 0.f;
#pragma unroll
        for (int c = 0; c < C_CLS; c++) if (c == lab) lp = l[c] - lse;
        accn += -lp;
    }
    red[tid] = accn;
    __syncthreads();
    for (int off = 128; off; off >>= 1) {
        if (tid < off) red[tid] += red[tid + off];
        __syncthreads();
    }
    if (tid == 0) out[(size_t)2 * ND + 1] = red[0] / (float)T_TRAIN * 0.1f;
}

// ---------------- launch ----------------
extern "C" void kernel_launch(void* const* d_in, const int* in_sizes, int n_in,
                              void* d_out, int out_size)
{
    const float* x_real     = (const float*)d_in[0];
    const float* x_imag     = (const float*)d_in[1];
    const float* adj        = (const float*)d_in[2];
    const float* theta_real = (const float*)d_in[3];
    const float* theta_imag = (const float*)d_in[4];
    const float* W_r        = (const float*)d_in[5];
    const float* b_r        = (const float*)d_in[6];
    const float* W_i        = (const float*)d_in[7];
    const float* b_i        = (const float*)d_in[8];
    const float* Wc_r       = (const float*)d_in[9];
    const float* bc_r       = (const float*)d_in[10];
    const float* Wc_i       = (const float*)d_in[11];
    const float* bc_i       = (const float*)d_in[12];
    const int*   labels     = (const int*)d_in[13];
    const int*   train_idx  = (const int*)d_in[14];
    float* out = (float*)d_out;

    cudaFuncSetAttribute(k_gemm1, cudaFuncAttributeMaxDynamicSharedMemorySize, SMEM_G1);

    k_build_wbig<<<256, 256>>>(W_r, W_i);
    k_node_prep<<<1024, 256>>>(x_real, x_imag, Wc_r, Wc_i, bc_r, bc_i,
                               theta_real, theta_imag);
    k_transp<<<dim3(256, 8), dim3(32, 8)>>>();
    k_gemm1<<<dim3(64, 1, NSPLIT), 256, SMEM_G1>>>(adj);
    k_combine2<<<4096, 256>>>();
    k_gemm_mlp<<<dim3(64, 2), 256>>>(b_r, b_i, x_real, x_imag, out);
    k_losses<<<1, 256>>>(theta_imag, labels, train_idx, out);
}